// round 14
// baseline (speedup 1.0000x reference)
#include <cuda_runtime.h>
#include <cuda.h>
#include <cuda_bf16.h>
#include <cuda_fp16.h>
#include <cstdint>

// ---------------- problem constants ----------------
#define MROWS 4096
#define NOUT  4096
#define KSEG  4096

// ---------------- GEMM tiling: cg2 pairs, 4-CTA cluster, B multicast across pairs -------
#define TILE_M 256           // per 2-CTA pair (128 M-rows per CTA)
#define TILE_N 256           // B split: 128 N-rows per CTA
#define TILE_K 64            // 64 fp16 = 128 B = one SW128 row
#define STAGES 6
#define KITERS (KSEG / TILE_K)     // 64

#define NCLUST 32                  // 32 clusters x 4 CTAs = 128 CTAs, single wave
#define NROUNDS 4                  // 128 work units (mpair, ntile) / 32 clusters

#define A_BYTES_CTA 16384          // 128 rows x 128 B
#define B_BYTES_CTA 16384          // 128 rows x 128 B
#define STAGE_BYTES (A_BYTES_CTA + B_BYTES_CTA)   // 32768
#define SMEM_TILES_OFF 1024
#define SMEM_TOTAL (SMEM_TILES_OFF + STAGES * STAGE_BYTES)   // 197632
#define PAIR_A_TX (2 * A_BYTES_CTA)  // 32768 on pair leader's fullA per stage

// idesc kind::f16, fp16 in, fp32 acc: dtype=F32(bit4), N/8<<17, M/16<<24
#define MMA_IDESC (0x10u | ((TILE_N / 8) << 17) | ((TILE_M / 16) << 24))

// ---------------- scratch ----------------
__device__ __align__(1024) __half g_A[(size_t)MROWS * KSEG];  // 32 MB
__device__ __align__(1024) __half g_B[(size_t)NOUT * KSEG];   // 32 MB

// ---------------- PTX helpers ----------------
__device__ __forceinline__ uint32_t smem_to_u32(const void* p) {
    uint32_t a;
    asm("{ .reg .u64 t; cvta.to.shared.u64 t, %1; cvt.u32.u64 %0, t; }" : "=r"(a) : "l"(p));
    return a;
}

__device__ __forceinline__ uint32_t cluster_rank() {
    uint32_t r;
    asm("mov.u32 %0, %%cluster_ctarank;" : "=r"(r));
    return r;
}

#define MBARRIER_INIT(addr, cnt) \
    asm volatile("mbarrier.init.shared.b64 [%0], %1;" :: "r"((uint32_t)(addr)), "r"((uint32_t)(cnt)) : "memory")

#define MBARRIER_EXPECT_TX(addr, bytes) \
    asm volatile("mbarrier.arrive.expect_tx.shared.b64 _, [%0], %1;" :: "r"((uint32_t)(addr)), "r"((uint32_t)(bytes)) : "memory")

// arrive on the same-offset mbarrier in cluster CTA `target_rank`
#define MBARRIER_ARRIVE_CLUSTER(local_addr, target_rank) \
    asm volatile( \
        "{\n\t.reg .b32 remAddr32;\n\t" \
        "mapa.shared::cluster.u32 remAddr32, %0, %1;\n\t" \
        "mbarrier.arrive.shared::cluster.b64 _, [remAddr32];\n\t}" \
        :: "r"((uint32_t)(local_addr)), "r"((uint32_t)(target_rank)) : "memory")

#define MBARRIER_WAIT_PARITY(addr, parity) do { \
    uint32_t _m = (uint32_t)(addr); uint32_t _p = (uint32_t)(parity); uint32_t _d; \
    asm volatile("{\n\t.reg .pred p;\n\t" \
        "mbarrier.try_wait.parity.acquire.cta.shared::cta.b64 p, [%1], %2;\n\t" \
        "selp.b32 %0, 1, 0, p;\n\t}" : "=r"(_d) : "r"(_m), "r"(_p) : "memory"); \
    if (!_d) { \
        asm volatile("{\n\t.reg .pred P1;\n\t" \
            "WL_%=:\n\t" \
            "mbarrier.try_wait.parity.acquire.cta.shared::cta.b64 P1, [%0], %1, 0x989680;\n\t" \
            "@P1 bra.uni WD_%=;\n\t" \
            "bra.uni WL_%=;\n\t" \
            "WD_%=:\n\t}" :: "r"(_m), "r"(_p) : "memory"); \
    } \
} while (0)

#define FENCE_PROXY_ASYNC() asm volatile("fence.proxy.async.shared::cta;" ::: "memory")

#define CLUSTER_SYNC() do { \
    asm volatile("barrier.cluster.arrive.aligned;" ::: "memory"); \
    asm volatile("barrier.cluster.wait.aligned;" ::: "memory"); \
} while (0)

// -------- tcgen05 cg2 (sm_103a-only) --------
#define TCGEN05_ALLOC_CG2(smem_addr, ncols) \
    asm volatile("tcgen05.alloc.cta_group::2.sync.aligned.shared::cta.b32 [%0], %1;" \
        :: "r"((uint32_t)(smem_addr)), "r"((uint32_t)(ncols)) : "memory")

#define TCGEN05_DEALLOC_CG2(tmem, ncols) \
    asm volatile("tcgen05.dealloc.cta_group::2.sync.aligned.b32 %0, %1;" :: "r"(tmem), "r"((uint32_t)(ncols)))

#define TCGEN05_RELINQUISH_CG2() \
    asm volatile("tcgen05.relinquish_alloc_permit.cta_group::2.sync.aligned;")

#define TCGEN05_COMMIT_MC_CG2(mbar, mask) \
    asm volatile("tcgen05.commit.cta_group::2.mbarrier::arrive::one.shared::cluster.multicast::cluster.b64 [%0], %1;" \
        :: "r"((uint32_t)(mbar)), "h"((uint16_t)(mask)) : "memory")

#define TCGEN05_FENCE_AFTER()  asm volatile("tcgen05.fence::after_thread_sync;" ::: "memory")
#define TCGEN05_FENCE_BEFORE() asm volatile("tcgen05.fence::before_thread_sync;" ::: "memory")
#define TCGEN05_WAIT_LD()      asm volatile("tcgen05.wait::ld.sync.aligned;" ::: "memory")

#define TCGEN05_LD_32X32B_X32(r, tmem_addr) \
    asm volatile( \
        "tcgen05.ld.sync.aligned.32x32b.x32.b32 " \
        "{%0, %1, %2, %3, %4, %5, %6, %7, " \
        " %8, %9, %10, %11, %12, %13, %14, %15, " \
        " %16, %17, %18, %19, %20, %21, %22, %23, " \
        " %24, %25, %26, %27, %28, %29, %30, %31}, [%32];" \
        : "=r"((r)[0]),  "=r"((r)[1]),  "=r"((r)[2]),  "=r"((r)[3]), \
          "=r"((r)[4]),  "=r"((r)[5]),  "=r"((r)[6]),  "=r"((r)[7]), \
          "=r"((r)[8]),  "=r"((r)[9]),  "=r"((r)[10]), "=r"((r)[11]), \
          "=r"((r)[12]), "=r"((r)[13]), "=r"((r)[14]), "=r"((r)[15]), \
          "=r"((r)[16]), "=r"((r)[17]), "=r"((r)[18]), "=r"((r)[19]), \
          "=r"((r)[20]), "=r"((r)[21]), "=r"((r)[22]), "=r"((r)[23]), \
          "=r"((r)[24]), "=r"((r)[25]), "=r"((r)[26]), "=r"((r)[27]), \
          "=r"((r)[28]), "=r"((r)[29]), "=r"((r)[30]), "=r"((r)[31]) \
        : "r"(tmem_addr))

static constexpr uint64_t SMEM_DESC_BASE_SW128 =
    (uint64_t(2) << 61) | (uint64_t(1) << 46) | (uint64_t(64) << 32) | (uint64_t(1) << 16);
#define MAKE_SMEM_DESC(base_addr) (SMEM_DESC_BASE_SW128 | ((uint64_t)((base_addr) >> 4) & 0x3FFF))

// cg2 TMA: both CTAs of a pair execute; complete_tx targets the pair LEADER's barrier
// (Sm100MmaPeerBitMask: clear bit 24 = rank LSB of the local barrier address).
__device__ __forceinline__ void tma_load_2d_cg2(uint32_t smem_addr, const void* tmap,
                                                int32_t cx, int32_t cy, uint32_t mbar) {
    asm volatile(
        "{\n\t.reg .b32 lb;\n\t"
        "and.b32 lb, %4, 0xFEFFFFFF;\n\t"
        "cp.async.bulk.tensor.2d.cta_group::2.shared::cluster.global.tile.mbarrier::complete_tx::bytes "
        "[%0], [%1, {%2, %3}], [lb];\n\t}"
        :: "r"(smem_addr), "l"(tmap), "r"(cx), "r"(cy), "r"(mbar) : "memory");
}

// multicast TMA: deliver tile + complete_tx to same smem offset in every masked CTA
__device__ __forceinline__ void tma_load_2d_mc(uint32_t smem_addr, const void* tmap,
                                               int32_t cx, int32_t cy, uint32_t mbar,
                                               uint16_t mask) {
    asm volatile(
        "cp.async.bulk.tensor.2d.shared::cluster.global.tile.mbarrier::complete_tx::bytes.multicast::cluster "
        "[%0], [%1, {%2, %3}], [%4], %5;"
        :: "r"(smem_addr), "l"(tmap), "r"(cx), "r"(cy), "r"(mbar), "h"(mask) : "memory");
}

#if defined(__CUDA_ARCH__) && defined(__CUDA_ARCH_FEAT_SM103_ALL)
__device__ __forceinline__ void mma_f16_ss_cg2(uint32_t d_tmem, uint64_t a_desc, uint64_t b_desc,
                                               uint32_t idesc, bool acc) {
    uint32_t en = acc ? 1u : 0u;
    asm volatile(
        "{\n\t.reg .pred p;\n\tsetp.ne.u32 p, %4, 0;\n\t"
        "tcgen05.mma.cta_group::2.kind::f16 [%0], %1, %2, %3, "
        "{%5, %5, %5, %5, %5, %5, %5, %5}, p;\n\t}"
        :: "r"(d_tmem), "l"(a_desc), "l"(b_desc), "r"(idesc), "r"(en), "r"(0u) : "memory");
}
#endif

// ============ fused prologue (R13): dq and cvt roles interleaved across blocks ==========
#define PREP_BLOCKS 5120
__global__ void __launch_bounds__(256) prep_kernel(const float* __restrict__ x,
                                                   const int* __restrict__ qw,
                                                   const int* __restrict__ qz,
                                                   const float* __restrict__ sc) {
    extern __shared__ uint4 cells[];   // 32 KB (dq blocks only)
    const int t = threadIdx.x;
    const int d = (int)blockIdx.x / 5;
    const int r = (int)blockIdx.x % 5;
    if (r == 0) {
        const int n0  = (d & 63) * 64;
        const int kp0 = (d >> 6) * 32;
#pragma unroll
        for (int i = 0; i < 8; i++) {
            int idx  = t + 256 * i;
            int kp_l = idx >> 6;
            int n_l  = idx & 63;
            int kp   = kp0 + kp_l;
            int n    = n0 + n_l;
            int g    = kp >> 4;
            unsigned w  = (unsigned)qw[(size_t)kp * NOUT + n];
            unsigned zw = (unsigned)qz[(size_t)g * (NOUT / 8) + (n >> 3)];
            float z = (float)(((zw >> ((n & 7) * 4)) & 15u) + 1u);
            float s = sc[(size_t)g * NOUT + n];
            float nsz = -s * z;
            __half2 h2[4];
#pragma unroll
            for (int j = 0; j < 4; j++) {
                float flo = fmaf((float)((w >> (8 * j))     & 15u), s, nsz);
                float fhi = fmaf((float)((w >> (8 * j + 4)) & 15u), s, nsz);
                h2[j] = __floats2half2_rn(flo, fhi);
            }
            cells[kp_l * 64 + (n_l ^ kp_l)] = *reinterpret_cast<uint4*>(h2);
        }
        __syncthreads();
#pragma unroll
        for (int i = 0; i < 8; i++) {
            int n_l = i * 8 + (t >> 5);
            int c   = t & 31;
            uint4 v = cells[c * 64 + (n_l ^ c)];
            reinterpret_cast<uint4*>(g_B)[(size_t)(n0 + n_l) * (KSEG / 8) + kp0 + c] = v;
        }
    } else {
        const size_t base = (size_t)(d * 4 + (r - 1)) * 1024;
#pragma unroll
        for (int j = 0; j < 4; j++) {
            size_t i = base + t + j * 256;
            float4 v = reinterpret_cast<const float4*>(x)[i];
            __half2 h2[2];
            h2[0] = __floats2half2_rn(v.x, v.y);
            h2[1] = __floats2half2_rn(v.z, v.w);
            *reinterpret_cast<uint2*>(g_A + i * 4) = *reinterpret_cast<uint2*>(h2);
        }
    }
}

// ========== persistent GEMM: 32 clusters x 4 CTAs = 2 cg2 pairs sharing B via MC ==========
// Work unit wu = cid + t*32: mpair = wu&7, ntile = wu>>3. Pair p handles mtile = mpair*2+p.
// A: per-CTA cg2 TMA -> pair leader's fullA (expect_tx 32K).
// B: rank0 loads half0 MC->{0,2}, rank1 half1 MC->{1,3}; every CTA expect_tx(16K) on local
//    fullB. Odd ranks' wid5 forwards local fullB completion to pair leader's fullBf.
// empty: CTAs 0,1 (B producers) count=2 (both pair leaders commit); CTAs 2,3 count=1.
//        pair0 leader commits mask 0x3; pair1 leader commits mask 0xF.
// warps 0-3: epilogue, warp 4: producer, warp 5: MMA (even ranks) / B-forwarder (odd).
__global__ void __launch_bounds__(192, 1) __cluster_dims__(4, 1, 1) gemm_kernel(
    const __grid_constant__ CUtensorMap tmapA,
    const __grid_constant__ CUtensorMap tmapB,
    const float* __restrict__ bias,
    float* __restrict__ out)
{
#if defined(__CUDA_ARCH__) && defined(__CUDA_ARCH_FEAT_SM103_ALL)
    extern __shared__ __align__(1024) char smem[];
    uint32_t sb = smem_to_u32(smem);
    const int tid = threadIdx.x, wid = tid >> 5, lid = tid & 31;
    const int cid = blockIdx.y;            // cluster id 0..31
    const uint32_t rank = cluster_rank();  // 0..3
    const int p   = (int)(rank >> 1);      // pair 0 or 1
    const int sub = (int)(rank & 1);       // 0 = pair leader

    const uint32_t tmem_ptr_addr = sb + 0;
    auto fullA_bar = [&](int s) { return sb + 64  + s * 8; };
    auto fullB_bar = [&](int s) { return sb + 128 + s * 8; };
    auto fullBf_bar= [&](int s) { return sb + 192 + s * 8; };
    auto empty_bar = [&](int s) { return sb + 256 + s * 8; };
    auto done_bar  = [&](int b) { return sb + 320 + b * 8; };
    auto epi_free  = [&](int b) { return sb + 336 + b * 8; };
    auto stageA = [&](int s) { return sb + SMEM_TILES_OFF + s * STAGE_BYTES; };
    auto stageB = [&](int s) { return sb + SMEM_TILES_OFF + s * STAGE_BYTES + A_BYTES_CTA; };

    if (tid == 0) {
#pragma unroll
        for (int s = 0; s < STAGES; s++) {
            MBARRIER_INIT(fullA_bar(s), 1);
            MBARRIER_INIT(fullB_bar(s), 1);
            MBARRIER_INIT(fullBf_bar(s), 1);
            MBARRIER_INIT(empty_bar(s), (rank < 2) ? 2 : 1);
        }
        MBARRIER_INIT(done_bar(0), 1);
        MBARRIER_INIT(done_bar(1), 1);
        MBARRIER_INIT(epi_free(0), 8);        // pair's 8 epilogue warps
        MBARRIER_INIT(epi_free(1), 8);
        FENCE_PROXY_ASYNC();
    }
    if (wid == 5) {                            // pair-collective TMEM alloc (even/odd pairs)
        TCGEN05_ALLOC_CG2(tmem_ptr_addr, 512);
        TCGEN05_RELINQUISH_CG2();
    }
    __syncthreads();
    CLUSTER_SYNC();

    uint32_t tmem_base;
    asm volatile("ld.shared.b32 %0, [%1];" : "=r"(tmem_base) : "r"(tmem_ptr_addr));

    if (wid == 4 && lid == 0) {
        // ---- producer (all 4 CTAs) ----
        const uint16_t bmask = (uint16_t)(0x5u << rank);   // rank0: {0,2}, rank1: {1,3}
        int s = 0, eph = 1;
        for (int t = 0; t < NROUNDS; t++) {
            const int wu = cid + t * NCLUST;
            const int mtile = (wu & 7) * 2 + p;
            const int ntile = wu >> 3;
            const int mrow = mtile * TILE_M + sub * 128;
            const int nrow = ntile * TILE_N + (int)rank * 128;   // ranks 0,1 only
            for (int it = 0; it < KITERS; it++) {
                MBARRIER_WAIT_PARITY(empty_bar(s), eph);
                if (sub == 0)
                    MBARRIER_EXPECT_TX(fullA_bar(s), PAIR_A_TX);
                tma_load_2d_cg2(stageA(s), &tmapA, it * TILE_K, mrow, fullA_bar(s));
                MBARRIER_EXPECT_TX(fullB_bar(s), B_BYTES_CTA);
                if (rank < 2)
                    tma_load_2d_mc(stageB(s), &tmapB, it * TILE_K, nrow,
                                   fullB_bar(s), bmask);
                if (++s == STAGES) { s = 0; eph ^= 1; }
            }
        }
    } else if (wid == 5 && lid == 0 && sub == 0) {
        // ---- MMA issuer (pair leaders: ranks 0 and 2) ----
        const uint16_t emask = (p == 0) ? (uint16_t)0x3 : (uint16_t)0xF;
        const uint16_t pmask = (uint16_t)(0x3u << (2 * p));
        int s = 0, fph = 0;
        for (int t = 0; t < NROUNDS; t++) {
            const int b = t & 1, u = t >> 1;
            MBARRIER_WAIT_PARITY(epi_free(b), (u & 1) ^ 1);
            const uint32_t acc = tmem_base + b * 256;
            for (int it = 0; it < KITERS; it++) {
                MBARRIER_WAIT_PARITY(fullA_bar(s), fph);
                MBARRIER_WAIT_PARITY(fullB_bar(s), fph);    // B half in own smem
                MBARRIER_WAIT_PARITY(fullBf_bar(s), fph);   // B half in odd peer's smem
                uint64_t ad = MAKE_SMEM_DESC(stageA(s));
                uint64_t bd = MAKE_SMEM_DESC(stageB(s));
#pragma unroll
                for (int k = 0; k < 4; k++)   // 4 x K16; +2 = +32 B desc step
                    mma_f16_ss_cg2(acc, ad + k * 2, bd + k * 2, MMA_IDESC,
                                   !(it == 0 && k == 0));
                TCGEN05_COMMIT_MC_CG2(empty_bar(s), emask);
                if (++s == STAGES) { s = 0; fph ^= 1; }
            }
            TCGEN05_COMMIT_MC_CG2(done_bar(b), pmask);
        }
    } else if (wid == 5 && lid == 0 && sub == 1) {
        // ---- B-forwarder (odd ranks): local fullB -> pair leader's fullBf ----
        int s = 0, fph = 0;
        for (int i = 0; i < NROUNDS * KITERS; i++) {
            MBARRIER_WAIT_PARITY(fullB_bar(s), fph);
            MBARRIER_ARRIVE_CLUSTER(fullBf_bar(s), rank - 1);
            if (++s == STAGES) { s = 0; fph ^= 1; }
        }
    } else if (wid < 4) {
        // ---- epilogue (all CTAs): each reads its own TMEM M-half ----
        for (int t = 0; t < NROUNDS; t++) {
            const int b = t & 1, u = t >> 1;
            MBARRIER_WAIT_PARITY(done_bar(b), u & 1);
            TCGEN05_FENCE_AFTER();
            const int wu = cid + t * NCLUST;
            const int mtile = (wu & 7) * 2 + p;
            const int ntile = wu >> 3;
            const int m = mtile * TILE_M + sub * 128 + wid * 32 + lid;
            const int nbase = ntile * TILE_N;
            float* orow = out + (size_t)m * NOUT + nbase;
            const uint32_t acc = tmem_base + b * 256;
#pragma unroll
            for (int cb = 0; cb < TILE_N / 32; cb++) {
                uint32_t r[32];
                TCGEN05_LD_32X32B_X32(r, acc + cb * 32);
                TCGEN05_WAIT_LD();
                const int n0 = nbase + cb * 32;
#pragma unroll
                for (int i = 0; i < 32; i += 4) {
                    float4 b4 = *reinterpret_cast<const float4*>(bias + n0 + i);
                    float4 v;
                    v.x = __uint_as_float(r[i + 0]) + b4.x;
                    v.y = __uint_as_float(r[i + 1]) + b4.y;
                    v.z = __uint_as_float(r[i + 2]) + b4.z;
                    v.w = __uint_as_float(r[i + 3]) + b4.w;
                    *reinterpret_cast<float4*>(orow + cb * 32 + i) = v;
                }
            }
            TCGEN05_FENCE_BEFORE();
            if (lid == 0) MBARRIER_ARRIVE_CLUSTER(epi_free(b), 2 * p);  // pair leader
        }
    }

    __syncthreads();
    if (wid == 5) TCGEN05_DEALLOC_CG2(tmem_base, 512);
    CLUSTER_SYNC();
#endif  // __CUDA_ARCH_FEAT_SM103_ALL
}

// ---------------- fallback path (non-'a' cubin only) ----------------
__global__ void __launch_bounds__(256) cvt_x_fb(const float* __restrict__ x) {
    size_t i = (size_t)blockIdx.x * blockDim.x + threadIdx.x;
    float4 v = reinterpret_cast<const float4*>(x)[i];
    __half h[4];
    h[0] = __float2half_rn(v.x);
    h[1] = __float2half_rn(v.y);
    h[2] = __float2half_rn(v.z);
    h[3] = __float2half_rn(v.w);
    *reinterpret_cast<uint2*>(g_A + i * 4) = *reinterpret_cast<uint2*>(h);
}

__global__ void __launch_bounds__(256) dequant_fb(const int* __restrict__ qw,
                                                  const int* __restrict__ qz,
                                                  const float* __restrict__ sc) {
    int i = blockIdx.x * blockDim.x + threadIdx.x;
    int n  = i & (NOUT - 1);
    int kp = i >> 12;
    int g  = kp >> 4;
    unsigned w  = (unsigned)qw[(size_t)kp * NOUT + n];
    unsigned zw = (unsigned)qz[(size_t)g * (NOUT / 8) + (n >> 3)];
    float z = (float)(((zw >> ((n & 7) * 4)) & 15u) + 1u);
    float s = sc[(size_t)g * NOUT + n];
    __half h[8];
#pragma unroll
    for (int j = 0; j < 8; j++) {
        float wv = (float)((w >> (4 * j)) & 15u);
        h[j] = __float2half_rn(s * (wv - z));
    }
    *reinterpret_cast<uint4*>(g_B + (size_t)n * KSEG + (size_t)kp * 8) =
        *reinterpret_cast<uint4*>(h);
}

#define FB_TM 128
#define FB_TN 128
#define FB_TK 32

__global__ void __launch_bounds__(256) gemm_fallback(const float* __restrict__ bias,
                                                     float* __restrict__ out) {
#if defined(__CUDA_ARCH__) && !defined(__CUDA_ARCH_FEAT_SM103_ALL)
    __shared__ __half sA[FB_TK][FB_TM + 4];
    __shared__ __half sB[FB_TK][FB_TN + 4];
    const int tid = threadIdx.x;
    const int m0 = blockIdx.y * FB_TM, n0 = blockIdx.x * FB_TN;
    const int tm = (tid >> 4) * 8, tn = (tid & 15) * 8;
    float acc[8][8] = {};
    for (int k0 = 0; k0 < KSEG; k0 += FB_TK) {
        __syncthreads();
        for (int idx = tid; idx < FB_TM * FB_TK / 8; idx += 256) {
            int row = idx >> 2;
            int kc  = (idx & 3) * 8;
            __half ta[8], tb[8];
            *reinterpret_cast<uint4*>(ta) =
                *reinterpret_cast<const uint4*>(&g_A[(size_t)(m0 + row) * KSEG + k0 + kc]);
            *reinterpret_cast<uint4*>(tb) =
                *reinterpret_cast<const uint4*>(&g_B[(size_t)(n0 + row) * KSEG + k0 + kc]);
#pragma unroll
            for (int j = 0; j < 8; j++) { sA[kc + j][row] = ta[j]; sB[kc + j][row] = tb[j]; }
        }
        __syncthreads();
#pragma unroll 4
        for (int kk = 0; kk < FB_TK; kk++) {
            float a[8], b[8];
#pragma unroll
            for (int j = 0; j < 8; j++) a[j] = __half2float(sA[kk][tm + j]);
#pragma unroll
            for (int j = 0; j < 8; j++) b[j] = __half2float(sB[kk][tn + j]);
#pragma unroll
            for (int i = 0; i < 8; i++)
#pragma unroll
                for (int j = 0; j < 8; j++) acc[i][j] += a[i] * b[j];
        }
    }
#pragma unroll
    for (int i = 0; i < 8; i++)
#pragma unroll
        for (int j = 0; j < 8; j++)
            out[(size_t)(m0 + tm + i) * NOUT + n0 + tn + j] = acc[i][j] + bias[n0 + tn + j];
#endif
}

// ---------------- host ----------------
typedef CUresult (*PFN_encodeTiled)(CUtensorMap*, CUtensorMapDataType, cuuint32_t, void*,
                                    const cuuint64_t*, const cuuint64_t*, const cuuint32_t*,
                                    const cuuint32_t*, CUtensorMapInterleave, CUtensorMapSwizzle,
                                    CUtensorMapL2promotion, CUtensorMapFloatOOBfill);

static void make_tmap(PFN_encodeTiled enc, CUtensorMap* m, void* ptr,
                      uint64_t rows, uint32_t box_rows) {
    cuuint64_t dims[2]    = {(cuuint64_t)KSEG, (cuuint64_t)rows};
    cuuint64_t strides[1] = {(cuuint64_t)KSEG * 2};
    cuuint32_t box[2]     = {(cuuint32_t)TILE_K, (cuuint32_t)box_rows};
    cuuint32_t es[2]      = {1, 1};
    enc(m, CU_TENSOR_MAP_DATA_TYPE_FLOAT16, 2, ptr, dims, strides, box, es,
        CU_TENSOR_MAP_INTERLEAVE_NONE, CU_TENSOR_MAP_SWIZZLE_128B,
        CU_TENSOR_MAP_L2_PROMOTION_L2_128B, CU_TENSOR_MAP_FLOAT_OOB_FILL_NONE);
}

extern "C" void kernel_launch(void* const* d_in, const int* in_sizes, int n_in,
                              void* d_out, int out_size) {
    const float* x    = (const float*)d_in[0];
    const int*   qw   = (const int*)d_in[1];
    const int*   qz   = (const int*)d_in[2];
    const float* sc   = (const float*)d_in[3];
    const float* bias = (const float*)d_in[4];
    float* out        = (float*)d_out;

    void* pA = nullptr; void* pB = nullptr;
    cudaGetSymbolAddress(&pA, g_A);
    cudaGetSymbolAddress(&pB, g_B);

    cudaFuncAttributes fa{};
    cudaFuncGetAttributes(&fa, gemm_kernel);
    const bool has_tc = (fa.numRegs > 32);

    if (has_tc) {
        void* fn = nullptr;
        cudaDriverEntryPointQueryResult qr;
        cudaGetDriverEntryPointByVersion("cuTensorMapEncodeTiled", &fn, 12000,
                                         cudaEnableDefault, &qr);
        PFN_encodeTiled enc = (PFN_encodeTiled)fn;

        CUtensorMap tA, tB;
        make_tmap(enc, &tA, pA, MROWS, 128);   // A: 128-row half-tiles
        make_tmap(enc, &tB, pB, NOUT, 128);    // B: 128-row half-tiles (multicast)

        cudaFuncSetAttribute(gemm_kernel, cudaFuncAttributeMaxDynamicSharedMemorySize, SMEM_TOTAL);
        cudaFuncSetAttribute(prep_kernel, cudaFuncAttributeMaxDynamicSharedMemorySize, 32768);

        prep_kernel<<<PREP_BLOCKS, 256, 32768>>>(x, qw, qz, sc);

        gemm_kernel<<<dim3(4, NCLUST, 1), 192, SMEM_TOTAL>>>(tA, tB, bias, out);
    } else {
        cvt_x_fb<<<(MROWS * KSEG / 4) / 256, 256>>>(x);
        dequant_fb<<<(512 * NOUT) / 256, 256>>>(qw, qz, sc);
        gemm_fallback<<<dim3(NOUT / FB_TN, MROWS / FB_TM), 256>>>(bias, out);
    }
}

// round 15
// speedup vs baseline: 1.0084x; 1.0084x over previous
#include <cuda_runtime.h>
#include <cuda.h>
#include <cuda_bf16.h>
#include <cuda_fp16.h>
#include <cstdint>

// ---------------- problem constants ----------------
#define MROWS 4096
#define NOUT  4096
#define KSEG  4096

// ---------------- GEMM tiling (cg2 pair tiles, R13 shape, 7 stages) ----------------
#define TILE_M 256           // per 2-CTA pair (128 M-rows per CTA)
#define TILE_N 256           // B split: 128 N-rows per CTA
#define TILE_K 64            // 64 fp16 = 128 B = one SW128 row
#define STAGES 7             // 7 x 32 KB = 224 KB ring (+1 KB barriers) < 227 KB max
#define KITERS (KSEG / TILE_K)     // 64

#define NPAIRS 64                  // 64 clusters x 2 CTAs = 128 CTAs, single wave
#define NTILES_PER_PAIR 4          // 256 tiles of 256x256 / 64

#define A_BYTES_CTA 16384          // 128 rows x 128 B
#define B_BYTES_CTA 16384          // 128 rows x 128 B
#define STAGE_BYTES (A_BYTES_CTA + B_BYTES_CTA)   // 32768
#define SMEM_TILES_OFF 1024
#define SMEM_TOTAL (SMEM_TILES_OFF + STAGES * STAGE_BYTES)   // 230400 (fits 232448 max)
#define PAIR_TX (2 * STAGE_BYTES)  // 65536 bytes arrive on leader bar per stage

// idesc kind::f16, fp16 in, fp32 acc: dtype=F32(bit4), N/8<<17, M/16<<24
#define MMA_IDESC (0x10u | ((TILE_N / 8) << 17) | ((TILE_M / 16) << 24))

// ---------------- scratch ----------------
__device__ __align__(1024) __half g_A[(size_t)MROWS * KSEG];  // 32 MB
__device__ __align__(1024) __half g_B[(size_t)NOUT * KSEG];   // 32 MB

// ---------------- PTX helpers ----------------
__device__ __forceinline__ uint32_t smem_to_u32(const void* p) {
    uint32_t a;
    asm("{ .reg .u64 t; cvta.to.shared.u64 t, %1; cvt.u32.u64 %0, t; }" : "=r"(a) : "l"(p));
    return a;
}

__device__ __forceinline__ uint32_t cluster_rank() {
    uint32_t r;
    asm("mov.u32 %0, %%cluster_ctarank;" : "=r"(r));
    return r;
}

#define MBARRIER_INIT(addr, cnt) \
    asm volatile("mbarrier.init.shared.b64 [%0], %1;" :: "r"((uint32_t)(addr)), "r"((uint32_t)(cnt)) : "memory")

#define MBARRIER_EXPECT_TX(addr, bytes) \
    asm volatile("mbarrier.arrive.expect_tx.shared.b64 _, [%0], %1;" :: "r"((uint32_t)(addr)), "r"((uint32_t)(bytes)) : "memory")

// arrive on the same-offset mbarrier in cluster CTA `target_rank`
#define MBARRIER_ARRIVE_CLUSTER(local_addr, target_rank) \
    asm volatile( \
        "{\n\t.reg .b32 remAddr32;\n\t" \
        "mapa.shared::cluster.u32 remAddr32, %0, %1;\n\t" \
        "mbarrier.arrive.shared::cluster.b64 _, [remAddr32];\n\t}" \
        :: "r"((uint32_t)(local_addr)), "r"((uint32_t)(target_rank)) : "memory")

#define MBARRIER_WAIT_PARITY(addr, parity) do { \
    uint32_t _m = (uint32_t)(addr); uint32_t _p = (uint32_t)(parity); uint32_t _d; \
    asm volatile("{\n\t.reg .pred p;\n\t" \
        "mbarrier.try_wait.parity.acquire.cta.shared::cta.b64 p, [%1], %2;\n\t" \
        "selp.b32 %0, 1, 0, p;\n\t}" : "=r"(_d) : "r"(_m), "r"(_p) : "memory"); \
    if (!_d) { \
        asm volatile("{\n\t.reg .pred P1;\n\t" \
            "WL_%=:\n\t" \
            "mbarrier.try_wait.parity.acquire.cta.shared::cta.b64 P1, [%0], %1, 0x989680;\n\t" \
            "@P1 bra.uni WD_%=;\n\t" \
            "bra.uni WL_%=;\n\t" \
            "WD_%=:\n\t}" :: "r"(_m), "r"(_p) : "memory"); \
    } \
} while (0)

#define FENCE_PROXY_ASYNC() asm volatile("fence.proxy.async.shared::cta;" ::: "memory")

#define CLUSTER_SYNC() do { \
    asm volatile("barrier.cluster.arrive.aligned;" ::: "memory"); \
    asm volatile("barrier.cluster.wait.aligned;" ::: "memory"); \
} while (0)

// -------- tcgen05 cg2 (sm_103a-only) --------
#define TCGEN05_ALLOC_CG2(smem_addr, ncols) \
    asm volatile("tcgen05.alloc.cta_group::2.sync.aligned.shared::cta.b32 [%0], %1;" \
        :: "r"((uint32_t)(smem_addr)), "r"((uint32_t)(ncols)) : "memory")

#define TCGEN05_DEALLOC_CG2(tmem, ncols) \
    asm volatile("tcgen05.dealloc.cta_group::2.sync.aligned.b32 %0, %1;" :: "r"(tmem), "r"((uint32_t)(ncols)))

#define TCGEN05_RELINQUISH_CG2() \
    asm volatile("tcgen05.relinquish_alloc_permit.cta_group::2.sync.aligned;")

#define TCGEN05_COMMIT_MC_CG2(mbar, mask) \
    asm volatile("tcgen05.commit.cta_group::2.mbarrier::arrive::one.shared::cluster.multicast::cluster.b64 [%0], %1;" \
        :: "r"((uint32_t)(mbar)), "h"((uint16_t)(mask)) : "memory")

#define TCGEN05_FENCE_AFTER()  asm volatile("tcgen05.fence::after_thread_sync;" ::: "memory")
#define TCGEN05_FENCE_BEFORE() asm volatile("tcgen05.fence::before_thread_sync;" ::: "memory")
#define TCGEN05_WAIT_LD()      asm volatile("tcgen05.wait::ld.sync.aligned;" ::: "memory")

#define TCGEN05_LD_32X32B_X32(r, tmem_addr) \
    asm volatile( \
        "tcgen05.ld.sync.aligned.32x32b.x32.b32 " \
        "{%0, %1, %2, %3, %4, %5, %6, %7, " \
        " %8, %9, %10, %11, %12, %13, %14, %15, " \
        " %16, %17, %18, %19, %20, %21, %22, %23, " \
        " %24, %25, %26, %27, %28, %29, %30, %31}, [%32];" \
        : "=r"((r)[0]),  "=r"((r)[1]),  "=r"((r)[2]),  "=r"((r)[3]), \
          "=r"((r)[4]),  "=r"((r)[5]),  "=r"((r)[6]),  "=r"((r)[7]), \
          "=r"((r)[8]),  "=r"((r)[9]),  "=r"((r)[10]), "=r"((r)[11]), \
          "=r"((r)[12]), "=r"((r)[13]), "=r"((r)[14]), "=r"((r)[15]), \
          "=r"((r)[16]), "=r"((r)[17]), "=r"((r)[18]), "=r"((r)[19]), \
          "=r"((r)[20]), "=r"((r)[21]), "=r"((r)[22]), "=r"((r)[23]), \
          "=r"((r)[24]), "=r"((r)[25]), "=r"((r)[26]), "=r"((r)[27]), \
          "=r"((r)[28]), "=r"((r)[29]), "=r"((r)[30]), "=r"((r)[31]) \
        : "r"(tmem_addr))

static constexpr uint64_t SMEM_DESC_BASE_SW128 =
    (uint64_t(2) << 61) | (uint64_t(1) << 46) | (uint64_t(64) << 32) | (uint64_t(1) << 16);
#define MAKE_SMEM_DESC(base_addr) (SMEM_DESC_BASE_SW128 | ((uint64_t)((base_addr) >> 4) & 0x3FFF))

// cg2 TMA: both CTAs execute; complete_tx targets the LEADER's barrier
// (Sm100MmaPeerBitMask: clear bit 24 of the local barrier address).
__device__ __forceinline__ void tma_load_2d_cg2(uint32_t smem_addr, const void* tmap,
                                                int32_t cx, int32_t cy, uint32_t mbar) {
    asm volatile(
        "{\n\t.reg .b32 lb;\n\t"
        "and.b32 lb, %4, 0xFEFFFFFF;\n\t"
        "cp.async.bulk.tensor.2d.cta_group::2.shared::cluster.global.tile.mbarrier::complete_tx::bytes "
        "[%0], [%1, {%2, %3}], [lb];\n\t}"
        :: "r"(smem_addr), "l"(tmap), "r"(cx), "r"(cy), "r"(mbar) : "memory");
}

#if defined(__CUDA_ARCH__) && defined(__CUDA_ARCH_FEAT_SM103_ALL)
__device__ __forceinline__ void mma_f16_ss_cg2(uint32_t d_tmem, uint64_t a_desc, uint64_t b_desc,
                                               uint32_t idesc, bool acc) {
    uint32_t en = acc ? 1u : 0u;
    asm volatile(
        "{\n\t.reg .pred p;\n\tsetp.ne.u32 p, %4, 0;\n\t"
        "tcgen05.mma.cta_group::2.kind::f16 [%0], %1, %2, %3, "
        "{%5, %5, %5, %5, %5, %5, %5, %5}, p;\n\t}"
        :: "r"(d_tmem), "l"(a_desc), "l"(b_desc), "r"(idesc), "r"(en), "r"(0u) : "memory");
}
#endif

// ============ fused prologue (R13): dq and cvt roles interleaved across blocks ==========
#define PREP_BLOCKS 5120
__global__ void __launch_bounds__(256) prep_kernel(const float* __restrict__ x,
                                                   const int* __restrict__ qw,
                                                   const int* __restrict__ qz,
                                                   const float* __restrict__ sc) {
    extern __shared__ uint4 cells[];   // 32 KB (dq blocks only)
    const int t = threadIdx.x;
    const int d = (int)blockIdx.x / 5;
    const int r = (int)blockIdx.x % 5;
    if (r == 0) {
        const int n0  = (d & 63) * 64;
        const int kp0 = (d >> 6) * 32;
#pragma unroll
        for (int i = 0; i < 8; i++) {
            int idx  = t + 256 * i;
            int kp_l = idx >> 6;
            int n_l  = idx & 63;
            int kp   = kp0 + kp_l;
            int n    = n0 + n_l;
            int g    = kp >> 4;
            unsigned w  = (unsigned)qw[(size_t)kp * NOUT + n];
            unsigned zw = (unsigned)qz[(size_t)g * (NOUT / 8) + (n >> 3)];
            float z = (float)(((zw >> ((n & 7) * 4)) & 15u) + 1u);
            float s = sc[(size_t)g * NOUT + n];
            float nsz = -s * z;
            __half2 h2[4];
#pragma unroll
            for (int j = 0; j < 4; j++) {
                float flo = fmaf((float)((w >> (8 * j))     & 15u), s, nsz);
                float fhi = fmaf((float)((w >> (8 * j + 4)) & 15u), s, nsz);
                h2[j] = __floats2half2_rn(flo, fhi);
            }
            cells[kp_l * 64 + (n_l ^ kp_l)] = *reinterpret_cast<uint4*>(h2);
        }
        __syncthreads();
#pragma unroll
        for (int i = 0; i < 8; i++) {
            int n_l = i * 8 + (t >> 5);
            int c   = t & 31;
            uint4 v = cells[c * 64 + (n_l ^ c)];
            reinterpret_cast<uint4*>(g_B)[(size_t)(n0 + n_l) * (KSEG / 8) + kp0 + c] = v;
        }
    } else {
        const size_t base = (size_t)(d * 4 + (r - 1)) * 1024;
#pragma unroll
        for (int j = 0; j < 4; j++) {
            size_t i = base + t + j * 256;
            float4 v = reinterpret_cast<const float4*>(x)[i];
            __half2 h2[2];
            h2[0] = __floats2half2_rn(v.x, v.y);
            h2[1] = __floats2half2_rn(v.z, v.w);
            *reinterpret_cast<uint2*>(g_A + i * 4) = *reinterpret_cast<uint2*>(h2);
        }
    }
}

// ========== persistent cg2 GEMM (R13 structure, 7-stage ring) ==========
// Pair tile M256 x N256. CTA rank r: A rows [mtile*256 + r*128, +128),
// B rows [ntile*256 + r*128, +128) in its own SMEM; cg2 MMA reads both SMEMs.
// warps 0-3: epilogue (own TMEM M-half), warp 4: TMA producer, warp 5: MMA (leader only).
__global__ void __launch_bounds__(192, 1) __cluster_dims__(2, 1, 1) gemm_kernel(
    const __grid_constant__ CUtensorMap tmapA,
    const __grid_constant__ CUtensorMap tmapB,
    const float* __restrict__ bias,
    float* __restrict__ out)
{
#if defined(__CUDA_ARCH__) && defined(__CUDA_ARCH_FEAT_SM103_ALL)
    extern __shared__ __align__(1024) char smem[];
    uint32_t sb = smem_to_u32(smem);
    const int tid = threadIdx.x, wid = tid >> 5, lid = tid & 31;
    const int cid = blockIdx.y;            // pair id 0..63
    const uint32_t rank = cluster_rank();  // 0 = leader

    const uint32_t tmem_ptr_addr = sb + 0;
    auto full_bar  = [&](int s) { return sb + 64 + s * 8; };    // s < 7 -> up to 112
    auto empty_bar = [&](int s) { return sb + 128 + s * 8; };   // up to 176
    auto done_bar  = [&](int b) { return sb + 192 + b * 8; };
    auto epi_free  = [&](int b) { return sb + 208 + b * 8; };
    auto stageA = [&](int s) { return sb + SMEM_TILES_OFF + s * STAGE_BYTES; };
    auto stageB = [&](int s) { return sb + SMEM_TILES_OFF + s * STAGE_BYTES + A_BYTES_CTA; };

    if (tid == 0) {
#pragma unroll
        for (int s = 0; s < STAGES; s++) {
            MBARRIER_INIT(full_bar(s), 1);    // leader: expect_tx(64K) + 1 arrival
            MBARRIER_INIT(empty_bar(s), 1);   // 1 arrival via leader's cg2 commit multicast
        }
        MBARRIER_INIT(done_bar(0), 1);
        MBARRIER_INIT(done_bar(1), 1);
        MBARRIER_INIT(epi_free(0), 8);        // 8 epilogue warps across the pair
        MBARRIER_INIT(epi_free(1), 8);
        FENCE_PROXY_ASYNC();
    }
    if (wid == 5) {                            // pair-collective TMEM alloc
        TCGEN05_ALLOC_CG2(tmem_ptr_addr, 512); // 2 x 256-col accumulator buffers
        TCGEN05_RELINQUISH_CG2();
    }
    __syncthreads();
    CLUSTER_SYNC();   // peer barriers visible before any cg2 TMA / commit / mapa-arrive

    uint32_t tmem_base;
    asm volatile("ld.shared.b32 %0, [%1];" : "=r"(tmem_base) : "r"(tmem_ptr_addr));

    if (wid == 4 && lid == 0) {
        // ---- TMA producer (both CTAs): cg2 loads complete on leader's full_bar ----
        int s = 0, eph = 1;
        for (int t = 0; t < NTILES_PER_PAIR; t++) {
            const int st = cid + t * NPAIRS;              // 0..255
            const int mrow = (st & 15) * TILE_M + (int)rank * 128;
            const int nrow = (st >> 4) * TILE_N + (int)rank * 128;
            for (int it = 0; it < KITERS; it++) {
                MBARRIER_WAIT_PARITY(empty_bar(s), eph);
                if (rank == 0)
                    MBARRIER_EXPECT_TX(full_bar(s), PAIR_TX);   // 4 x 16 KB slices
                tma_load_2d_cg2(stageA(s), &tmapA, it * TILE_K, mrow, full_bar(s));
                tma_load_2d_cg2(stageB(s), &tmapB, it * TILE_K, nrow, full_bar(s));
                if (++s == STAGES) { s = 0; eph ^= 1; }
            }
        }
    } else if (wid == 5 && lid == 0 && rank == 0) {
        // ---- MMA issuer (leader only) ----
        int s = 0, fph = 0;
        for (int t = 0; t < NTILES_PER_PAIR; t++) {
            const int b = t & 1, u = t >> 1;
            MBARRIER_WAIT_PARITY(epi_free(b), (u & 1) ^ 1);   // both CTAs' epilogues done
            const uint32_t acc = tmem_base + b * 256;
            for (int it = 0; it < KITERS; it++) {
                MBARRIER_WAIT_PARITY(full_bar(s), fph);
                uint64_t ad = MAKE_SMEM_DESC(stageA(s));
                uint64_t bd = MAKE_SMEM_DESC(stageB(s));
#pragma unroll
                for (int k = 0; k < 4; k++)   // 4 x K16; +2 = +32 B desc step
                    mma_f16_ss_cg2(acc, ad + k * 2, bd + k * 2, MMA_IDESC,
                                   !(it == 0 && k == 0));
                TCGEN05_COMMIT_MC_CG2(empty_bar(s), 0x3);   // free stage in both CTAs
                if (++s == STAGES) { s = 0; fph ^= 1; }
            }
            TCGEN05_COMMIT_MC_CG2(done_bar(b), 0x3);        // tile done -> both CTAs
        }
    } else if (wid < 4) {
        // ---- epilogue (both CTAs): each reads its own TMEM M-half ----
        for (int t = 0; t < NTILES_PER_PAIR; t++) {
            const int b = t & 1, u = t >> 1;
            MBARRIER_WAIT_PARITY(done_bar(b), u & 1);
            TCGEN05_FENCE_AFTER();
            const int st = cid + t * NPAIRS;
            const int m = (st & 15) * TILE_M + (int)rank * 128 + wid * 32 + lid;
            const int nbase = (st >> 4) * TILE_N;
            float* orow = out + (size_t)m * NOUT + nbase;
            const uint32_t acc = tmem_base + b * 256;
#pragma unroll
            for (int cb = 0; cb < TILE_N / 32; cb++) {
                uint32_t r[32];
                TCGEN05_LD_32X32B_X32(r, acc + cb * 32);
                TCGEN05_WAIT_LD();
                const int n0 = nbase + cb * 32;
#pragma unroll
                for (int i = 0; i < 32; i += 4) {
                    float4 b4 = *reinterpret_cast<const float4*>(bias + n0 + i);
                    float4 v;
                    v.x = __uint_as_float(r[i + 0]) + b4.x;
                    v.y = __uint_as_float(r[i + 1]) + b4.y;
                    v.z = __uint_as_float(r[i + 2]) + b4.z;
                    v.w = __uint_as_float(r[i + 3]) + b4.w;
                    *reinterpret_cast<float4*>(orow + cb * 32 + i) = v;
                }
            }
            TCGEN05_FENCE_BEFORE();
            if (lid == 0) MBARRIER_ARRIVE_CLUSTER(epi_free(b), 0);   // arrive on leader
        }
    }

    __syncthreads();
    if (wid == 5) TCGEN05_DEALLOC_CG2(tmem_base, 512);
    CLUSTER_SYNC();   // peer may still touch this CTA's SMEM / barriers
#endif  // __CUDA_ARCH_FEAT_SM103_ALL
}

// ---------------- fallback path (non-'a' cubin only) ----------------
__global__ void __launch_bounds__(256) cvt_x_fb(const float* __restrict__ x) {
    size_t i = (size_t)blockIdx.x * blockDim.x + threadIdx.x;
    float4 v = reinterpret_cast<const float4*>(x)[i];
    __half h[4];
    h[0] = __float2half_rn(v.x);
    h[1] = __float2half_rn(v.y);
    h[2] = __float2half_rn(v.z);
    h[3] = __float2half_rn(v.w);
    *reinterpret_cast<uint2*>(g_A + i * 4) = *reinterpret_cast<uint2*>(h);
}

__global__ void __launch_bounds__(256) dequant_fb(const int* __restrict__ qw,
                                                  const int* __restrict__ qz,
                                                  const float* __restrict__ sc) {
    int i = blockIdx.x * blockDim.x + threadIdx.x;
    int n  = i & (NOUT - 1);
    int kp = i >> 12;
    int g  = kp >> 4;
    unsigned w  = (unsigned)qw[(size_t)kp * NOUT + n];
    unsigned zw = (unsigned)qz[(size_t)g * (NOUT / 8) + (n >> 3)];
    float z = (float)(((zw >> ((n & 7) * 4)) & 15u) + 1u);
    float s = sc[(size_t)g * NOUT + n];
    __half h[8];
#pragma unroll
    for (int j = 0; j < 8; j++) {
        float wv = (float)((w >> (4 * j)) & 15u);
        h[j] = __float2half_rn(s * (wv - z));
    }
    *reinterpret_cast<uint4*>(g_B + (size_t)n * KSEG + (size_t)kp * 8) =
        *reinterpret_cast<uint4*>(h);
}

#define FB_TM 128
#define FB_TN 128
#define FB_TK 32

__global__ void __launch_bounds__(256) gemm_fallback(const float* __restrict__ bias,
                                                     float* __restrict__ out) {
#if defined(__CUDA_ARCH__) && !defined(__CUDA_ARCH_FEAT_SM103_ALL)
    __shared__ __half sA[FB_TK][FB_TM + 4];
    __shared__ __half sB[FB_TK][FB_TN + 4];
    const int tid = threadIdx.x;
    const int m0 = blockIdx.y * FB_TM, n0 = blockIdx.x * FB_TN;
    const int tm = (tid >> 4) * 8, tn = (tid & 15) * 8;
    float acc[8][8] = {};
    for (int k0 = 0; k0 < KSEG; k0 += FB_TK) {
        __syncthreads();
        for (int idx = tid; idx < FB_TM * FB_TK / 8; idx += 256) {
            int row = idx >> 2;
            int kc  = (idx & 3) * 8;
            __half ta[8], tb[8];
            *reinterpret_cast<uint4*>(ta) =
                *reinterpret_cast<const uint4*>(&g_A[(size_t)(m0 + row) * KSEG + k0 + kc]);
            *reinterpret_cast<uint4*>(tb) =
                *reinterpret_cast<const uint4*>(&g_B[(size_t)(n0 + row) * KSEG + k0 + kc]);
#pragma unroll
            for (int j = 0; j < 8; j++) { sA[kc + j][row] = ta[j]; sB[kc + j][row] = tb[j]; }
        }
        __syncthreads();
#pragma unroll 4
        for (int kk = 0; kk < FB_TK; kk++) {
            float a[8], b[8];
#pragma unroll
            for (int j = 0; j < 8; j++) a[j] = __half2float(sA[kk][tm + j]);
#pragma unroll
            for (int j = 0; j < 8; j++) b[j] = __half2float(sB[kk][tn + j]);
#pragma unroll
            for (int i = 0; i < 8; i++)
#pragma unroll
                for (int j = 0; j < 8; j++) acc[i][j] += a[i] * b[j];
        }
    }
#pragma unroll
    for (int i = 0; i < 8; i++)
#pragma unroll
        for (int j = 0; j < 8; j++)
            out[(size_t)(m0 + tm + i) * NOUT + n0 + tn + j] = acc[i][j] + bias[n0 + tn + j];
#endif
}

// ---------------- host ----------------
typedef CUresult (*PFN_encodeTiled)(CUtensorMap*, CUtensorMapDataType, cuuint32_t, void*,
                                    const cuuint64_t*, const cuuint64_t*, const cuuint32_t*,
                                    const cuuint32_t*, CUtensorMapInterleave, CUtensorMapSwizzle,
                                    CUtensorMapL2promotion, CUtensorMapFloatOOBfill);

static void make_tmap(PFN_encodeTiled enc, CUtensorMap* m, void* ptr,
                      uint64_t rows, uint32_t box_rows) {
    cuuint64_t dims[2]    = {(cuuint64_t)KSEG, (cuuint64_t)rows};
    cuuint64_t strides[1] = {(cuuint64_t)KSEG * 2};
    cuuint32_t box[2]     = {(cuuint32_t)TILE_K, (cuuint32_t)box_rows};
    cuuint32_t es[2]      = {1, 1};
    enc(m, CU_TENSOR_MAP_DATA_TYPE_FLOAT16, 2, ptr, dims, strides, box, es,
        CU_TENSOR_MAP_INTERLEAVE_NONE, CU_TENSOR_MAP_SWIZZLE_128B,
        CU_TENSOR_MAP_L2_PROMOTION_L2_128B, CU_TENSOR_MAP_FLOAT_OOB_FILL_NONE);
}

extern "C" void kernel_launch(void* const* d_in, const int* in_sizes, int n_in,
                              void* d_out, int out_size) {
    const float* x    = (const float*)d_in[0];
    const int*   qw   = (const int*)d_in[1];
    const int*   qz   = (const int*)d_in[2];
    const float* sc   = (const float*)d_in[3];
    const float* bias = (const float*)d_in[4];
    float* out        = (float*)d_out;

    void* pA = nullptr; void* pB = nullptr;
    cudaGetSymbolAddress(&pA, g_A);
    cudaGetSymbolAddress(&pB, g_B);

    // Which cubin variant loaded? The tcgen05 kernel has a large register
    // footprint; the empty shell does not.
    cudaFuncAttributes fa{};
    cudaFuncGetAttributes(&fa, gemm_kernel);
    const bool has_tc = (fa.numRegs > 32);

    if (has_tc) {
        void* fn = nullptr;
        cudaDriverEntryPointQueryResult qr;
        cudaGetDriverEntryPointByVersion("cuTensorMapEncodeTiled", &fn, 12000,
                                         cudaEnableDefault, &qr);
        PFN_encodeTiled enc = (PFN_encodeTiled)fn;

        CUtensorMap tA, tB;
        make_tmap(enc, &tA, pA, MROWS, 128);   // A: 128-row half-tiles
        make_tmap(enc, &tB, pB, NOUT, 128);    // B: 128-row half-tiles

        cudaFuncSetAttribute(gemm_kernel, cudaFuncAttributeMaxDynamicSharedMemorySize, SMEM_TOTAL);
        cudaFuncSetAttribute(prep_kernel, cudaFuncAttributeMaxDynamicSharedMemorySize, 32768);

        prep_kernel<<<PREP_BLOCKS, 256, 32768>>>(x, qw, qz, sc);

        gemm_kernel<<<dim3(2, NPAIRS, 1), 192, SMEM_TOTAL>>>(tA, tB, bias, out);
    } else {
        cvt_x_fb<<<(MROWS * KSEG / 4) / 256, 256>>>(x);
        dequant_fb<<<(512 * NOUT) / 256, 256>>>(qw, qz, sc);
        gemm_fallback<<<dim3(NOUT / FB_TN, MROWS / FB_TM), 256>>>(bias, out);
    }
}